// round 1
// baseline (speedup 1.0000x reference)
#include <cuda_runtime.h>
#include <cstdint>

// Problem constants
constexpr int Bb = 4, Ss = 2048, Dd = 1024, Hh = 16, DK = 64;

// Scratch (static device arrays: allocation-free rule)
static __device__ float g_Qb[Bb * Ss * Dd];
static __device__ float g_Kb[Bb * Ss * Dd];
static __device__ float g_Vb[Bb * Ss * Dd];
static __device__ float g_Ab[Bb * Ss * Dd];

#define DEVI __device__ __forceinline__

DEVI float tf_rna(float x) {
    uint32_t r;
    asm("cvt.rna.tf32.f32 %0, %1;" : "=r"(r) : "f"(x));
    return __uint_as_float(r);
}
DEVI float ex2f(float x) {
    float r;
    asm("ex2.approx.f32 %0, %1;" : "=f"(r) : "f"(x));
    return r;
}
// Round fp32 bits to nearest tf32 (HMMA ignores the low 13 bits; +0x1000 is RN).
DEVI uint32_t rnd13(float f) { return __float_as_uint(f) + 0x1000u; }

DEVI void mma8(float* c, uint32_t a0, uint32_t a1, uint32_t a2, uint32_t a3,
               uint32_t b0, uint32_t b1) {
    asm volatile(
        "mma.sync.aligned.m16n8k8.row.col.f32.tf32.tf32.f32 "
        "{%0,%1,%2,%3},{%4,%5,%6,%7},{%8,%9},{%0,%1,%2,%3};"
        : "+f"(c[0]), "+f"(c[1]), "+f"(c[2]), "+f"(c[3])
        : "r"(a0), "r"(a1), "r"(a2), "r"(a3), "r"(b0), "r"(b1));
}

DEVI void cp16(void* smem, const void* g) {
    uint32_t s = (uint32_t)__cvta_generic_to_shared(smem);
    asm volatile("cp.async.cg.shared.global [%0], [%1], 16;\n" ::"r"(s), "l"(g));
}
DEVI void cpcommit() { asm volatile("cp.async.commit_group;\n"); }
DEVI void cpwait0() { asm volatile("cp.async.wait_group 0;\n" ::: "memory"); }
DEVI void cpwait1() { asm volatile("cp.async.wait_group 1;\n" ::: "memory"); }

// ===========================================================================
// tf32 GEMM: C[M,N] = A[M,K] * B[K,N] + bias[N]
// CTA tile 128x128x32, 8 warps (2x4), warp tile 64x32, double-buffered cp.async
// ===========================================================================
constexpr int BM = 128, BN = 128, BK = 32;
constexpr int AST = 36;   // padded A smem row stride (floats) - conflict free, 16B aligned
constexpr int BST = 132;  // padded B smem row stride
constexpr int GEMM_SMEM = (2 * BM * AST + 2 * BK * BST) * 4;

DEVI void gemm_load(float* As, float* Bs, const float* A, const float* Bw,
                    int bm, int bn, int kt, int buf, int tid, int N, int K) {
    const int arow = tid >> 3, acol = (tid & 7) << 2;
    const int brow = tid >> 5, bcol = (tid & 31) << 2;
    const float* Ag = A + (size_t)bm * K + kt * BK;
#pragma unroll
    for (int i = 0; i < 4; i++) {
        int r = arow + i * 32;
        cp16(&As[buf * BM * AST + r * AST + acol], Ag + (size_t)r * K + acol);
    }
    const float* Bg = Bw + (size_t)(kt * BK) * N + bn;
#pragma unroll
    for (int i = 0; i < 4; i++) {
        int r = brow + i * 8;
        cp16(&Bs[buf * BK * BST + r * BST + bcol], Bg + (size_t)r * N + bcol);
    }
    cpcommit();
}

__global__ void __launch_bounds__(256, 2)
gemm_tf32(const float* __restrict__ A, const float* __restrict__ Bw,
          const float* __restrict__ bias, float* __restrict__ C,
          int M, int N, int K) {
    extern __shared__ float sm[];
    float* As = sm;                  // [2][BM*AST]
    float* Bs = sm + 2 * BM * AST;   // [2][BK*BST]

    const int tid = threadIdx.x, lane = tid & 31, w = tid >> 5;
    const int wr = w >> 2, wc = w & 3, g = lane >> 2, tg = lane & 3;
    const int bm = blockIdx.y * BM, bn = blockIdx.x * BN;
    const int NK = K / BK;

    float acc[4][4][4];
#pragma unroll
    for (int i = 0; i < 4; i++)
#pragma unroll
        for (int j = 0; j < 4; j++)
#pragma unroll
            for (int r = 0; r < 4; r++) acc[i][j][r] = 0.f;

    gemm_load(As, Bs, A, Bw, bm, bn, 0, 0, tid, N, K);

    for (int kt = 0; kt < NK; kt++) {
        if (kt + 1 < NK) {
            gemm_load(As, Bs, A, Bw, bm, bn, kt + 1, (kt + 1) & 1, tid, N, K);
            cpwait1();
        } else {
            cpwait0();
        }
        __syncthreads();

        const int buf = kt & 1;
        const float* Ab_ = As + buf * BM * AST + (wr * 64) * AST;
        const float* Bb_ = Bs + buf * BK * BST + wc * 32;
#pragma unroll
        for (int ks = 0; ks < 4; ks++) {
            uint32_t af[4][4];
#pragma unroll
            for (int mt = 0; mt < 4; mt++) {
                const float* p = Ab_ + (mt * 16 + g) * AST + ks * 8 + tg;
                af[mt][0] = rnd13(p[0]);
                af[mt][1] = rnd13(p[8 * AST]);
                af[mt][2] = rnd13(p[4]);
                af[mt][3] = rnd13(p[8 * AST + 4]);
            }
#pragma unroll
            for (int nt = 0; nt < 4; nt++) {
                const float* q = Bb_ + (ks * 8 + tg) * BST + nt * 8 + g;
                uint32_t b0 = rnd13(q[0]);
                uint32_t b1 = rnd13(q[4 * BST]);
#pragma unroll
                for (int mt = 0; mt < 4; mt++)
                    mma8(acc[mt][nt], af[mt][0], af[mt][1], af[mt][2], af[mt][3], b0, b1);
            }
        }
        __syncthreads();
    }

    // Epilogue: + bias, store
#pragma unroll
    for (int mt = 0; mt < 4; mt++) {
        int r0 = bm + wr * 64 + mt * 16 + g;
#pragma unroll
        for (int nt = 0; nt < 4; nt++) {
            int col = bn + wc * 32 + nt * 8 + tg * 2;
            float b0v = bias[col], b1v = bias[col + 1];
            *(float2*)(C + (size_t)r0 * N + col) =
                make_float2(acc[mt][nt][0] + b0v, acc[mt][nt][1] + b1v);
            *(float2*)(C + (size_t)(r0 + 8) * N + col) =
                make_float2(acc[mt][nt][2] + b0v, acc[mt][nt][3] + b1v);
        }
    }
}

// ===========================================================================
// Flash attention (tf32 mma): one CTA = 256 query rows of one (b,h).
// Q/K/V in [B,S,D] layout (head h at column offset h*64, row stride 1024).
// Online softmax in registers (rows live inside one warp; quad shuffles).
// exp folded into exp2: Q pre-scaled by log2(e)/sqrt(DK).
// ===========================================================================
constexpr int QT = 256, KT = 64, STp = 68;
constexpr int ATTN_SMEM = (QT * STp + QT * STp + KT * STp + KT * STp) * 4;

__global__ void __launch_bounds__(256, 1)
attn_kernel(const float* __restrict__ Qg, const float* __restrict__ Kg,
            const float* __restrict__ Vg, float* __restrict__ Og) {
    extern __shared__ float sm[];
    float* Qs = sm;                   // [QT][STp]
    float* Ps = sm + QT * STp;        // [QT][STp]
    float* Ks = sm + 2 * QT * STp;    // [KT][STp]
    float* Vs = Ks + KT * STp;        // [KT][STp]

    const int tid = threadIdx.x, lane = tid & 31, w = tid >> 5;
    const int g = lane >> 2, tg = lane & 3;
    const int wrow = w * 32;
    const int bh = blockIdx.y, b = bh >> 4, h = bh & 15;
    const int q0 = blockIdx.x * QT;
    const size_t baseQ = ((size_t)b * Ss + q0) * Dd + h * DK;
    const size_t baseKV = ((size_t)b * Ss) * Dd + h * DK;

    const float qscale = 1.4426950408889634f * 0.125f;  // log2(e)/sqrt(64)

    // Load + prescale + round Q tile
#pragma unroll
    for (int i = 0; i < 16; i++) {
        int idx = tid + i * 256;
        int r = idx >> 4, c = (idx & 15) << 2;
        float4 v = *(const float4*)(Qg + baseQ + (size_t)r * Dd + c);
        float4 t;
        t.x = tf_rna(v.x * qscale); t.y = tf_rna(v.y * qscale);
        t.z = tf_rna(v.z * qscale); t.w = tf_rna(v.w * qscale);
        *(float4*)(Qs + r * STp + c) = t;
    }

    float ofr[2][8][4];
#pragma unroll
    for (int i = 0; i < 2; i++)
#pragma unroll
        for (int j = 0; j < 8; j++)
#pragma unroll
            for (int r = 0; r < 4; r++) ofr[i][j][r] = 0.f;
    float mrow[2][2] = {{-1e30f, -1e30f}, {-1e30f, -1e30f}};
    float lrow[2][2] = {{0.f, 0.f}, {0.f, 0.f}};

    for (int kt = 0; kt < Ss / KT; kt++) {
        __syncthreads();  // protect Ks/Vs (prev iter readers done)
        const size_t kbase = baseKV + (size_t)(kt * KT) * Dd;
#pragma unroll
        for (int i = 0; i < 4; i++) {
            int idx = tid + i * 256;
            int r = idx >> 4, c = (idx & 15) << 2;
            float4 kk = *(const float4*)(Kg + kbase + (size_t)r * Dd + c);
            float4 vv = *(const float4*)(Vg + kbase + (size_t)r * Dd + c);
            float4 tk, tv;
            tk.x = tf_rna(kk.x); tk.y = tf_rna(kk.y); tk.z = tf_rna(kk.z); tk.w = tf_rna(kk.w);
            tv.x = tf_rna(vv.x); tv.y = tf_rna(vv.y); tv.z = tf_rna(vv.z); tv.w = tf_rna(vv.w);
            *(float4*)(Ks + r * STp + c) = tk;
            *(float4*)(Vs + r * STp + c) = tv;
        }
        __syncthreads();

        // ---- S = (Q*scale) @ K^T  (in log2-domain for exp2 softmax)
        float sfr[2][8][4];
#pragma unroll
        for (int i = 0; i < 2; i++)
#pragma unroll
            for (int j = 0; j < 8; j++)
#pragma unroll
                for (int r = 0; r < 4; r++) sfr[i][j][r] = 0.f;

#pragma unroll
        for (int ks = 0; ks < 8; ks++) {
            uint32_t af[2][4];
#pragma unroll
            for (int mt = 0; mt < 2; mt++) {
                const float* p = Qs + (wrow + mt * 16 + g) * STp + ks * 8 + tg;
                af[mt][0] = __float_as_uint(p[0]);
                af[mt][1] = __float_as_uint(p[8 * STp]);
                af[mt][2] = __float_as_uint(p[4]);
                af[mt][3] = __float_as_uint(p[8 * STp + 4]);
            }
#pragma unroll
            for (int nt = 0; nt < 8; nt++) {
                const float* q = Ks + (nt * 8 + g) * STp + ks * 8 + tg;
                uint32_t b0 = __float_as_uint(q[0]);
                uint32_t b1 = __float_as_uint(q[4]);
                mma8(sfr[0][nt], af[0][0], af[0][1], af[0][2], af[0][3], b0, b1);
                mma8(sfr[1][nt], af[1][0], af[1][1], af[1][2], af[1][3], b0, b1);
            }
        }

        // ---- online softmax (rows g / g+8 of each 16-row mtile; quad reduce)
#pragma unroll
        for (int mt = 0; mt < 2; mt++) {
#pragma unroll
            for (int hf = 0; hf < 2; hf++) {
                float mx = -1e30f;
#pragma unroll
                for (int nt = 0; nt < 8; nt++)
                    mx = fmaxf(mx, fmaxf(sfr[mt][nt][2 * hf], sfr[mt][nt][2 * hf + 1]));
                mx = fmaxf(mx, __shfl_xor_sync(0xffffffffu, mx, 1));
                mx = fmaxf(mx, __shfl_xor_sync(0xffffffffu, mx, 2));
                float mo = mrow[mt][hf];
                float mn = fmaxf(mo, mx);
                float al = ex2f(mo - mn);
                float sum = 0.f;
#pragma unroll
                for (int nt = 0; nt < 8; nt++) {
                    float p0 = tf_rna(ex2f(sfr[mt][nt][2 * hf] - mn));
                    float p1 = tf_rna(ex2f(sfr[mt][nt][2 * hf + 1] - mn));
                    sfr[mt][nt][2 * hf] = p0;
                    sfr[mt][nt][2 * hf + 1] = p1;
                    sum += p0 + p1;
                }
                sum += __shfl_xor_sync(0xffffffffu, sum, 1);
                sum += __shfl_xor_sync(0xffffffffu, sum, 2);
                lrow[mt][hf] = lrow[mt][hf] * al + sum;
                mrow[mt][hf] = mn;
#pragma unroll
                for (int nt = 0; nt < 8; nt++) {
                    ofr[mt][nt][2 * hf] *= al;
                    ofr[mt][nt][2 * hf + 1] *= al;
                }
            }
        }

        // ---- stage P through smem (C-layout -> A-layout transpose)
#pragma unroll
        for (int mt = 0; mt < 2; mt++)
#pragma unroll
            for (int nt = 0; nt < 8; nt++) {
                *(float2*)(Ps + (wrow + mt * 16 + g) * STp + nt * 8 + tg * 2) =
                    make_float2(sfr[mt][nt][0], sfr[mt][nt][1]);
                *(float2*)(Ps + (wrow + mt * 16 + g + 8) * STp + nt * 8 + tg * 2) =
                    make_float2(sfr[mt][nt][2], sfr[mt][nt][3]);
            }
        __syncwarp();

        // ---- O += P @ V
#pragma unroll
        for (int ks = 0; ks < 8; ks++) {
            uint32_t af[2][4];
#pragma unroll
            for (int mt = 0; mt < 2; mt++) {
                const float* p = Ps + (wrow + mt * 16 + g) * STp + ks * 8 + tg;
                af[mt][0] = __float_as_uint(p[0]);
                af[mt][1] = __float_as_uint(p[8 * STp]);
                af[mt][2] = __float_as_uint(p[4]);
                af[mt][3] = __float_as_uint(p[8 * STp + 4]);
            }
#pragma unroll
            for (int nt = 0; nt < 8; nt++) {
                const float* q = Vs + (ks * 8 + tg) * STp + nt * 8 + g;
                uint32_t b0 = __float_as_uint(q[0]);
                uint32_t b1 = __float_as_uint(q[4 * STp]);
                mma8(ofr[0][nt], af[0][0], af[0][1], af[0][2], af[0][3], b0, b1);
                mma8(ofr[1][nt], af[1][0], af[1][1], af[1][2], af[1][3], b0, b1);
            }
        }
    }

    // ---- normalize + write [B,S,D]
#pragma unroll
    for (int mt = 0; mt < 2; mt++)
#pragma unroll
        for (int hf = 0; hf < 2; hf++) {
            float inv = 1.f / lrow[mt][hf];
            int r = q0 + wrow + mt * 16 + g + hf * 8;
            float* op = Og + ((size_t)b * Ss + r) * Dd + h * DK;
#pragma unroll
            for (int nt = 0; nt < 8; nt++)
                *(float2*)(op + nt * 8 + tg * 2) =
                    make_float2(ofr[mt][nt][2 * hf] * inv, ofr[mt][nt][2 * hf + 1] * inv);
        }
}

// ===========================================================================
// Launch
// ===========================================================================
extern "C" void kernel_launch(void* const* d_in, const int* in_sizes, int n_in,
                              void* d_out, int out_size) {
    const float* q  = (const float*)d_in[0];
    const float* k  = (const float*)d_in[1];
    const float* v  = (const float*)d_in[2];
    const float* wq = (const float*)d_in[3];
    const float* bq = (const float*)d_in[4];
    const float* wk = (const float*)d_in[5];
    const float* bk = (const float*)d_in[6];
    const float* wv = (const float*)d_in[7];
    const float* bv = (const float*)d_in[8];
    const float* wo = (const float*)d_in[9];
    const float* bo = (const float*)d_in[10];
    float* out = (float*)d_out;

    float *Qb, *Kb, *Vb, *Ab;
    cudaGetSymbolAddress((void**)&Qb, g_Qb);
    cudaGetSymbolAddress((void**)&Kb, g_Kb);
    cudaGetSymbolAddress((void**)&Vb, g_Vb);
    cudaGetSymbolAddress((void**)&Ab, g_Ab);

    cudaFuncSetAttribute(gemm_tf32, cudaFuncAttributeMaxDynamicSharedMemorySize, GEMM_SMEM);
    cudaFuncSetAttribute(attn_kernel, cudaFuncAttributeMaxDynamicSharedMemorySize, ATTN_SMEM);

    dim3 gg(Dd / BN, (Bb * Ss) / BM);  // (8, 64)
    gemm_tf32<<<gg, 256, GEMM_SMEM>>>(q, wq, bq, Qb, Bb * Ss, Dd, Dd);
    gemm_tf32<<<gg, 256, GEMM_SMEM>>>(k, wk, bk, Kb, Bb * Ss, Dd, Dd);
    gemm_tf32<<<gg, 256, GEMM_SMEM>>>(v, wv, bv, Vb, Bb * Ss, Dd, Dd);

    dim3 ga(Ss / QT, Bb * Hh);  // (8, 64)
    attn_kernel<<<ga, 256, ATTN_SMEM>>>(Qb, Kb, Vb, Ab);

    gemm_tf32<<<gg, 256, GEMM_SMEM>>>(Ab, wo, bo, out, Bb * Ss, Dd, Dd);
}

// round 5
// speedup vs baseline: 1.7013x; 1.7013x over previous
#include <cuda_runtime.h>
#include <cuda_fp16.h>
#include <cstdint>

// Problem constants
constexpr int Bb = 4, Ss = 2048, Dd = 1024, Hh = 16, DK = 64;
constexpr int Mrows = Bb * Ss;  // 8192

// Scratch (static device arrays: allocation-free rule). All fp16 activations.
static __device__ __half g_Qh[Mrows * Dd];
static __device__ __half g_Kh[Mrows * Dd];
static __device__ __half g_Vh[Mrows * Dd];
static __device__ __half g_Ah[Mrows * Dd];   // attention output
static __device__ __half g_Xh[Mrows * Dd];   // converted activation input (reused)
static __device__ __half g_Wh[Dd * Dd];      // converted + transposed weight [n][k] (reused)

#define DEVI __device__ __forceinline__

DEVI float ex2f(float x) {
    float r;
    asm("ex2.approx.f32 %0, %1;" : "=f"(r) : "f"(x));
    return r;
}

// fp16 MMA: D(16x8,f32) += A(16x16,f16 row) * B(16x8,f16 col)
DEVI void mma_h(float* c, uint32_t a0, uint32_t a1, uint32_t a2, uint32_t a3,
                uint32_t b0, uint32_t b1) {
    asm volatile(
        "mma.sync.aligned.m16n8k16.row.col.f32.f16.f16.f32 "
        "{%0,%1,%2,%3},{%4,%5,%6,%7},{%8,%9},{%0,%1,%2,%3};"
        : "+f"(c[0]), "+f"(c[1]), "+f"(c[2]), "+f"(c[3])
        : "r"(a0), "r"(a1), "r"(a2), "r"(a3), "r"(b0), "r"(b1));
}

DEVI void cp16(void* smem, const void* g) {
    uint32_t s = (uint32_t)__cvta_generic_to_shared(smem);
    asm volatile("cp.async.cg.shared.global [%0], [%1], 16;\n" ::"r"(s), "l"(g));
}
DEVI void cpcommit() { asm volatile("cp.async.commit_group;\n"); }
DEVI void cpwait0() { asm volatile("cp.async.wait_group 0;\n" ::: "memory"); }
DEVI void cpwait1() { asm volatile("cp.async.wait_group 1;\n" ::: "memory"); }

DEVI uint32_t h2u(__half2 h) { return *reinterpret_cast<uint32_t*>(&h); }

// ===========================================================================
// Conversion passes (fp32 -> fp16 RN)
// ===========================================================================
__global__ void __launch_bounds__(256)
cvt_h(const float4* __restrict__ in, __half2* __restrict__ out, int n4) {
    for (int i = blockIdx.x * blockDim.x + threadIdx.x; i < n4; i += gridDim.x * blockDim.x) {
        float4 v = in[i];
        out[2 * i + 0] = __floats2half2_rn(v.x, v.y);
        out[2 * i + 1] = __floats2half2_rn(v.z, v.w);
    }
}

// Wh[n][k] = (half)W[k][n] : transpose to K-major for the B fragment
__global__ void cvt_transpose_h(const float* __restrict__ W, __half* __restrict__ Wt) {
    __shared__ float t[32][33];
    int k0 = blockIdx.y * 32, n0 = blockIdx.x * 32;
    int tx = threadIdx.x, ty = threadIdx.y;
#pragma unroll
    for (int i = 0; i < 32; i += 8)
        t[ty + i][tx] = W[(size_t)(k0 + ty + i) * Dd + n0 + tx];
    __syncthreads();
#pragma unroll
    for (int i = 0; i < 32; i += 8)
        Wt[(size_t)(n0 + ty + i) * Dd + k0 + tx] = __float2half_rn(t[tx][ty + i]);
}

// ===========================================================================
// fp16 GEMM: C[M,1024] = A[M,1024](half,row) @ Wt^T(half,[n][k]) + bias(f32)
// CTA 128x128x32, 8 warps (2x4), warp 64x32, double-buffered cp.async.
// OutT = __half (projections) or float (final output).
// ===========================================================================
constexpr int HST = 40;   // smem row stride in halves (80B; conflict-free)
constexpr int GEMM_SMEM_H = 2 * (128 * HST + 128 * HST) * 2;  // 40960 B

DEVI void gemm_load_h(__half* As, __half* Bs, const __half* A, const __half* Bw,
                      int bm, int bn, int kt, int buf, int tid) {
#pragma unroll
    for (int i = 0; i < 2; i++) {
        int u = tid + 256 * i;
        int row = u >> 2, cc = (u & 3) * 8;
        cp16(&As[buf * 128 * HST + row * HST + cc],
             A + (size_t)(bm + row) * Dd + kt * 32 + cc);
        cp16(&Bs[buf * 128 * HST + row * HST + cc],
             Bw + (size_t)(bn + row) * Dd + kt * 32 + cc);
    }
    cpcommit();
}

template <typename OutT>
__global__ void __launch_bounds__(256, 2)
gemm_h(const __half* __restrict__ A, const __half* __restrict__ Bw,
       const float* __restrict__ bias, OutT* __restrict__ C) {
    extern __shared__ __half smh[];
    __half* As = smh;                    // [2][128*HST]
    __half* Bs = smh + 2 * 128 * HST;    // [2][128*HST]

    const int tid = threadIdx.x, lane = tid & 31, w = tid >> 5;
    const int wr = w >> 2, wc = w & 3, g = lane >> 2, tg = lane & 3;
    const int bm = blockIdx.y * 128, bn = blockIdx.x * 128;
    const int NK = Dd / 32;

    float acc[4][4][4];
#pragma unroll
    for (int i = 0; i < 4; i++)
#pragma unroll
        for (int j = 0; j < 4; j++)
#pragma unroll
            for (int r = 0; r < 4; r++) acc[i][j][r] = 0.f;

    gemm_load_h(As, Bs, A, Bw, bm, bn, 0, 0, tid);

    for (int kt = 0; kt < NK; kt++) {
        if (kt + 1 < NK) {
            gemm_load_h(As, Bs, A, Bw, bm, bn, kt + 1, (kt + 1) & 1, tid);
            cpwait1();
        } else {
            cpwait0();
        }
        __syncthreads();

        const int buf = kt & 1;
        const __half* Ab_ = As + buf * 128 * HST + (wr * 64) * HST;
        const __half* Bb_ = Bs + buf * 128 * HST + (wc * 32) * HST;
#pragma unroll
        for (int ks = 0; ks < 2; ks++) {
            uint32_t af[4][4];
#pragma unroll
            for (int mt = 0; mt < 4; mt++) {
                const __half* p = Ab_ + (mt * 16 + g) * HST + ks * 16 + 2 * tg;
                af[mt][0] = *(const uint32_t*)(p);
                af[mt][1] = *(const uint32_t*)(p + 8 * HST);
                af[mt][2] = *(const uint32_t*)(p + 8);
                af[mt][3] = *(const uint32_t*)(p + 8 * HST + 8);
            }
#pragma unroll
            for (int nt = 0; nt < 4; nt++) {
                const __half* q = Bb_ + (nt * 8 + g) * HST + ks * 16 + 2 * tg;
                uint32_t b0 = *(const uint32_t*)(q);
                uint32_t b1 = *(const uint32_t*)(q + 8);
#pragma unroll
                for (int mt = 0; mt < 4; mt++)
                    mma_h(acc[mt][nt], af[mt][0], af[mt][1], af[mt][2], af[mt][3], b0, b1);
            }
        }
        __syncthreads();
    }

    // Epilogue: + bias, store (half2 or float2)
#pragma unroll
    for (int mt = 0; mt < 4; mt++) {
        int r0 = bm + wr * 64 + mt * 16 + g;
#pragma unroll
        for (int nt = 0; nt < 4; nt++) {
            int col = bn + wc * 32 + nt * 8 + 2 * tg;
            float b0v = bias[col], b1v = bias[col + 1];
            if (sizeof(OutT) == 2) {
                __half2* c0p = (__half2*)((__half*)C + (size_t)r0 * Dd + col);
                __half2* c1p = (__half2*)((__half*)C + (size_t)(r0 + 8) * Dd + col);
                *c0p = __floats2half2_rn(acc[mt][nt][0] + b0v, acc[mt][nt][1] + b1v);
                *c1p = __floats2half2_rn(acc[mt][nt][2] + b0v, acc[mt][nt][3] + b1v);
            } else {
                *(float2*)((float*)C + (size_t)r0 * Dd + col) =
                    make_float2(acc[mt][nt][0] + b0v, acc[mt][nt][1] + b1v);
                *(float2*)((float*)C + (size_t)(r0 + 8) * Dd + col) =
                    make_float2(acc[mt][nt][2] + b0v, acc[mt][nt][3] + b1v);
            }
        }
    }
}

// ===========================================================================
// Flash attention, fp16 mma (m16n8k16). One CTA = 256 query rows of one (b,h).
// Q/K/V/O in [B,S,D] half layout (head h at column h*64).
// K tile register-prefetched; V stored transposed in smem for the PV B-frag.
// ===========================================================================
constexpr int QT = 256, KT = 64;
constexpr int QSP = 72, KSP = 72, PSP = 72, VSP = 70;  // smem strides (halves)
constexpr int ATTN_SMEM = (QT * QSP + QT * PSP + KT * KSP + KT * VSP) * 2;

__global__ void __launch_bounds__(256, 1)
attn_h(const __half* __restrict__ Qg, const __half* __restrict__ Kg,
       const __half* __restrict__ Vg, __half* __restrict__ Og) {
    extern __shared__ __half smh[];
    __half* Qs = smh;                    // [QT][QSP]
    __half* Ps = Qs + QT * QSP;          // [QT][PSP]
    __half* Ks = Ps + QT * PSP;          // [KT][KSP]  row = kv pos, col = dim
    __half* Vt = Ks + KT * KSP;          // [64 dims][VSP] transposed V

    const int tid = threadIdx.x, lane = tid & 31, w = tid >> 5;
    const int g = lane >> 2, tg = lane & 3;
    const int wrow = w * 32;
    const int bh = blockIdx.y, b = bh >> 4, h = bh & 15;
    const int q0 = blockIdx.x * QT;
    const size_t baseQ = ((size_t)b * Ss + q0) * Dd + h * DK;
    const size_t baseKV = ((size_t)b * Ss) * Dd + h * DK;

    const float qs = 1.4426950408889634f * 0.125f;  // log2(e)/sqrt(64)

    const uint4* Qv = (const uint4*)(Qg + baseQ);
    const uint4* Kv = (const uint4*)(Kg + baseKV);
    const uint4* Vv = (const uint4*)(Vg + baseKV);

    // ---- load Q tile (256 x 64 halves)
#pragma unroll
    for (int i = 0; i < 8; i++) {
        int u = tid + i * 256;
        int r = u >> 3, cu = u & 7;
        uint4 t = Qv[(size_t)r * 128 + cu];
        *(uint4*)(Qs + r * QSP + cu * 8) = t;
    }

    uint4 kreg[2], vreg[2];
    // prologue: tile 0 into regs, then smem
#pragma unroll
    for (int i = 0; i < 2; i++) {
        int u = tid + i * 256;
        int r = u >> 3, cu = u & 7;
        kreg[i] = Kv[(size_t)r * 128 + cu];
        vreg[i] = Vv[(size_t)r * 128 + cu];
    }
#pragma unroll
    for (int i = 0; i < 2; i++) {
        int u = tid + i * 256;
        int r = u >> 3, cu = u & 7, c = cu * 8;
        *(uint4*)(Ks + r * KSP + c) = kreg[i];
#pragma unroll
        for (int j = 0; j < 4; j++) {
            uint32_t wv = (&vreg[i].x)[j];
            Vt[(c + 2 * j) * VSP + r] = __ushort_as_half((unsigned short)(wv & 0xffff));
            Vt[(c + 2 * j + 1) * VSP + r] = __ushort_as_half((unsigned short)(wv >> 16));
        }
    }
    __syncthreads();

    float ofr[2][8][4];
#pragma unroll
    for (int i = 0; i < 2; i++)
#pragma unroll
        for (int j = 0; j < 8; j++)
#pragma unroll
            for (int r = 0; r < 4; r++) ofr[i][j][r] = 0.f;
    float mrow[2][2] = {{-1e30f, -1e30f}, {-1e30f, -1e30f}};
    float lrow[2][2] = {{0.f, 0.f}, {0.f, 0.f}};

    const int NT = Ss / KT;  // 32
    for (int kt = 0; kt < NT; kt++) {
        // prefetch next K/V tile into registers (hidden behind compute)
        if (kt + 1 < NT) {
#pragma unroll
            for (int i = 0; i < 2; i++) {
                int u = tid + i * 256;
                int r = u >> 3, cu = u & 7;
                kreg[i] = Kv[(size_t)((kt + 1) * KT + r) * 128 + cu];
                vreg[i] = Vv[(size_t)((kt + 1) * KT + r) * 128 + cu];
            }
        }

        // ---- S = Q @ K^T (raw scores, fp32 accum)
        float sfr[2][8][4];
#pragma unroll
        for (int i = 0; i < 2; i++)
#pragma unroll
            for (int j = 0; j < 8; j++)
#pragma unroll
                for (int r = 0; r < 4; r++) sfr[i][j][r] = 0.f;

#pragma unroll
        for (int ks = 0; ks < 4; ks++) {
            uint32_t af[2][4];
#pragma unroll
            for (int mt = 0; mt < 2; mt++) {
                const __half* p = Qs + (wrow + mt * 16 + g) * QSP + ks * 16 + 2 * tg;
                af[mt][0] = *(const uint32_t*)(p);
                af[mt][1] = *(const uint32_t*)(p + 8 * QSP);
                af[mt][2] = *(const uint32_t*)(p + 8);
                af[mt][3] = *(const uint32_t*)(p + 8 * QSP + 8);
            }
#pragma unroll
            for (int nt = 0; nt < 8; nt++) {
                const __half* q = Ks + (nt * 8 + g) * KSP + ks * 16 + 2 * tg;
                uint32_t b0 = *(const uint32_t*)(q);
                uint32_t b1 = *(const uint32_t*)(q + 8);
                mma_h(sfr[0][nt], af[0][0], af[0][1], af[0][2], af[0][3], b0, b1);
                mma_h(sfr[1][nt], af[1][0], af[1][1], af[1][2], af[1][3], b0, b1);
            }
        }

        // ---- online softmax (scale folded into exp2: p = 2^((s-m)*qs))
#pragma unroll
        for (int mt = 0; mt < 2; mt++) {
#pragma unroll
            for (int hf = 0; hf < 2; hf++) {
                float mx = -1e30f;
#pragma unroll
                for (int nt = 0; nt < 8; nt++)
                    mx = fmaxf(mx, fmaxf(sfr[mt][nt][2 * hf], sfr[mt][nt][2 * hf + 1]));
                mx = fmaxf(mx, __shfl_xor_sync(0xffffffffu, mx, 1));
                mx = fmaxf(mx, __shfl_xor_sync(0xffffffffu, mx, 2));
                float mo = mrow[mt][hf];
                float mn = fmaxf(mo, mx);
                float mq = mn * qs;
                float al = ex2f(fmaf(mo, qs, -mq));
                float sum = 0.f;
#pragma unroll
                for (int nt = 0; nt < 8; nt++) {
                    float p0 = ex2f(fmaf(sfr[mt][nt][2 * hf], qs, -mq));
                    float p1 = ex2f(fmaf(sfr[mt][nt][2 * hf + 1], qs, -mq));
                    sfr[mt][nt][2 * hf] = p0;
                    sfr[mt][nt][2 * hf + 1] = p1;
                    sum += p0 + p1;
                }
                sum += __shfl_xor_sync(0xffffffffu, sum, 1);
                sum += __shfl_xor_sync(0xffffffffu, sum, 2);
                lrow[mt][hf] = lrow[mt][hf] * al + sum;
                mrow[mt][hf] = mn;
#pragma unroll
                for (int nt = 0; nt < 8; nt++) {
                    ofr[mt][nt][2 * hf] *= al;
                    ofr[mt][nt][2 * hf + 1] *= al;
                }
            }
        }

        // ---- stage P (half2) through smem
#pragma unroll
        for (int mt = 0; mt < 2; mt++)
#pragma unroll
            for (int nt = 0; nt < 8; nt++) {
                *(uint32_t*)(Ps + (wrow + mt * 16 + g) * PSP + nt * 8 + 2 * tg) =
                    h2u(__floats2half2_rn(sfr[mt][nt][0], sfr[mt][nt][1]));
                *(uint32_t*)(Ps + (wrow + mt * 16 + g + 8) * PSP + nt * 8 + 2 * tg) =
                    h2u(__floats2half2_rn(sfr[mt][nt][2], sfr[mt][nt][3]));
            }
        __syncwarp();

        // ---- O += P @ V   (B-frag from transposed V: consecutive kv at fixed dim)
#pragma unroll
        for (int ks = 0; ks < 4; ks++) {
            uint32_t af[2][4];
#pragma unroll
            for (int mt = 0; mt < 2; mt++) {
                const __half* p = Ps + (wrow + mt * 16 + g) * PSP + ks * 16 + 2 * tg;
                af[mt][0] = *(const uint32_t*)(p);
                af[mt][1] = *(const uint32_t*)(p + 8 * PSP);
                af[mt][2] = *(const uint32_t*)(p + 8);
                af[mt][3] = *(const uint32_t*)(p + 8 * PSP + 8);
            }
#pragma unroll
            for (int nt = 0; nt < 8; nt++) {
                const __half* q = Vt + (nt * 8 + g) * VSP + ks * 16 + 2 * tg;
                uint32_t b0 = *(const uint32_t*)(q);
                uint32_t b1 = *(const uint32_t*)(q + 8);
                mma_h(ofr[0][nt], af[0][0], af[0][1], af[0][2], af[0][3], b0, b1);
                mma_h(ofr[1][nt], af[1][0], af[1][1], af[1][2], af[1][3], b0, b1);
            }
        }

        // ---- publish next K/V tile
        if (kt + 1 < NT) {
            __syncthreads();
#pragma unroll
            for (int i = 0; i < 2; i++) {
                int u = tid + i * 256;
                int r = u >> 3, cu = u & 7, c = cu * 8;
                *(uint4*)(Ks + r * KSP + c) = kreg[i];
#pragma unroll
                for (int j = 0; j < 4; j++) {
                    uint32_t wv = (&vreg[i].x)[j];
                    Vt[(c + 2 * j) * VSP + r] = __ushort_as_half((unsigned short)(wv & 0xffff));
                    Vt[(c + 2 * j + 1) * VSP + r] = __ushort_as_half((unsigned short)(wv >> 16));
                }
            }
            __syncthreads();
        }
    }

    // ---- normalize + write [B,S,D] half
#pragma unroll
    for (int mt = 0; mt < 2; mt++)
#pragma unroll
        for (int hf = 0; hf < 2; hf++) {
            float inv = 1.f / lrow[mt][hf];
            int r = q0 + wrow + mt * 16 + g + hf * 8;
            __half* op = Og + ((size_t)b * Ss + r) * Dd + h * DK;
#pragma unroll
            for (int nt = 0; nt < 8; nt++)
                *(uint32_t*)(op + nt * 8 + 2 * tg) =
                    h2u(__floats2half2_rn(ofr[mt][nt][2 * hf] * inv,
                                          ofr[mt][nt][2 * hf + 1] * inv));
        }
}

// ===========================================================================
// Launch
// ===========================================================================
extern "C" void kernel_launch(void* const* d_in, const int* in_sizes, int n_in,
                              void* d_out, int out_size) {
    const float* q  = (const float*)d_in[0];
    const float* k  = (const float*)d_in[1];
    const float* v  = (const float*)d_in[2];
    const float* wq = (const float*)d_in[3];
    const float* bq = (const float*)d_in[4];
    const float* wk = (const float*)d_in[5];
    const float* bk = (const float*)d_in[6];
    const float* wv = (const float*)d_in[7];
    const float* bv = (const float*)d_in[8];
    const float* wo = (const float*)d_in[9];
    const float* bo = (const float*)d_in[10];
    float* out = (float*)d_out;

    __half *Qh, *Kh, *Vh, *Ah, *Xh, *Wh;
    cudaGetSymbolAddress((void**)&Qh, g_Qh);
    cudaGetSymbolAddress((void**)&Kh, g_Kh);
    cudaGetSymbolAddress((void**)&Vh, g_Vh);
    cudaGetSymbolAddress((void**)&Ah, g_Ah);
    cudaGetSymbolAddress((void**)&Xh, g_Xh);
    cudaGetSymbolAddress((void**)&Wh, g_Wh);

    cudaFuncSetAttribute(gemm_h<__half>, cudaFuncAttributeMaxDynamicSharedMemorySize, GEMM_SMEM_H);
    cudaFuncSetAttribute(gemm_h<float>, cudaFuncAttributeMaxDynamicSharedMemorySize, GEMM_SMEM_H);
    cudaFuncSetAttribute(attn_h, cudaFuncAttributeMaxDynamicSharedMemorySize, ATTN_SMEM);

    const int n4 = Mrows * Dd / 4;
    dim3 tgrid(Dd / 32, Dd / 32), tblk(32, 8);
    dim3 gg(Dd / 128, Mrows / 128);  // (8, 64)
    dim3 ga(Ss / QT, Bb * Hh);       // (8, 64)

    // Q projection
    cvt_transpose_h<<<tgrid, tblk>>>(wq, Wh);
    cvt_h<<<1184, 256>>>((const float4*)q, (__half2*)Xh, n4);
    gemm_h<__half><<<gg, 256, GEMM_SMEM_H>>>(Xh, Wh, bq, Qh);

    // K projection
    cvt_transpose_h<<<tgrid, tblk>>>(wk, Wh);
    cvt_h<<<1184, 256>>>((const float4*)k, (__half2*)Xh, n4);
    gemm_h<__half><<<gg, 256, GEMM_SMEM_H>>>(Xh, Wh, bk, Kh);

    // V projection
    cvt_transpose_h<<<tgrid, tblk>>>(wv, Wh);
    cvt_h<<<1184, 256>>>((const float4*)v, (__half2*)Xh, n4);
    gemm_h<__half><<<gg, 256, GEMM_SMEM_H>>>(Xh, Wh, bv, Vh);

    // Attention
    attn_h<<<ga, 256, ATTN_SMEM>>>(Qh, Kh, Vh, Ah);

    // Output projection (fp32 out)
    cvt_transpose_h<<<tgrid, tblk>>>(wo, Wh);
    gemm_h<float><<<gg, 256, GEMM_SMEM_H>>>(Ah, Wh, bo, out);
}

// round 6
// speedup vs baseline: 1.8302x; 1.0758x over previous
#include <cuda_runtime.h>
#include <cuda_fp16.h>
#include <cstdint>

// Problem constants
constexpr int Bb = 4, Ss = 2048, Dd = 1024, Hh = 16, DK = 64;
constexpr int Mrows = Bb * Ss;  // 8192

// Scratch (static device arrays: allocation-free rule). All fp16 activations.
static __device__ __half g_Qh[Mrows * Dd];
static __device__ __half g_Kh[Mrows * Dd];
static __device__ __half g_Vh[Mrows * Dd];
static __device__ __half g_Ah[Mrows * Dd];   // attention output
static __device__ __half g_Xh[Mrows * Dd];   // converted activation input (reused)
static __device__ __half g_Wh[Dd * Dd];      // converted + transposed weight [n][k] (reused)

#define DEVI __device__ __forceinline__

DEVI float ex2f(float x) {
    float r;
    asm("ex2.approx.f32 %0, %1;" : "=f"(r) : "f"(x));
    return r;
}

// fp16 MMA: D(16x8,f32) += A(16x16,f16 row) * B(16x8,f16 col)
DEVI void mma_h(float* c, uint32_t a0, uint32_t a1, uint32_t a2, uint32_t a3,
                uint32_t b0, uint32_t b1) {
    asm volatile(
        "mma.sync.aligned.m16n8k16.row.col.f32.f16.f16.f32 "
        "{%0,%1,%2,%3},{%4,%5,%6,%7},{%8,%9},{%0,%1,%2,%3};"
        : "+f"(c[0]), "+f"(c[1]), "+f"(c[2]), "+f"(c[3])
        : "r"(a0), "r"(a1), "r"(a2), "r"(a3), "r"(b0), "r"(b1));
}

DEVI void ldsm4(uint32_t& r0, uint32_t& r1, uint32_t& r2, uint32_t& r3, uint32_t saddr) {
    asm volatile("ldmatrix.sync.aligned.m8n8.x4.shared.b16 {%0,%1,%2,%3}, [%4];"
                 : "=r"(r0), "=r"(r1), "=r"(r2), "=r"(r3) : "r"(saddr));
}
DEVI void ldsm2(uint32_t& r0, uint32_t& r1, uint32_t saddr) {
    asm volatile("ldmatrix.sync.aligned.m8n8.x2.shared.b16 {%0,%1}, [%2];"
                 : "=r"(r0), "=r"(r1) : "r"(saddr));
}
DEVI void ldsm2t(uint32_t& r0, uint32_t& r1, uint32_t saddr) {
    asm volatile("ldmatrix.sync.aligned.m8n8.x2.trans.shared.b16 {%0,%1}, [%2];"
                 : "=r"(r0), "=r"(r1) : "r"(saddr));
}

DEVI void cp16(void* smem, const void* g) {
    uint32_t s = (uint32_t)__cvta_generic_to_shared(smem);
    asm volatile("cp.async.cg.shared.global [%0], [%1], 16;\n" ::"r"(s), "l"(g));
}
DEVI void cpcommit() { asm volatile("cp.async.commit_group;\n"); }
DEVI void cpwait0() { asm volatile("cp.async.wait_group 0;\n" ::: "memory"); }
DEVI void cpwait1() { asm volatile("cp.async.wait_group 1;\n" ::: "memory"); }

DEVI uint32_t h2u(__half2 h) { return *reinterpret_cast<uint32_t*>(&h); }
DEVI uint32_t smem_u32(const void* p) {
    uint32_t a;
    asm("{ .reg .u64 t; cvta.to.shared.u64 t, %1; cvt.u32.u64 %0, t; }" : "=r"(a) : "l"(p));
    return a;
}

// ===========================================================================
// Conversion passes (fp32 -> fp16 RN)
// ===========================================================================
__global__ void __launch_bounds__(256)
cvt_h(const float4* __restrict__ in, __half2* __restrict__ out, int n4) {
    for (int i = blockIdx.x * blockDim.x + threadIdx.x; i < n4; i += gridDim.x * blockDim.x) {
        float4 v = in[i];
        out[2 * i + 0] = __floats2half2_rn(v.x, v.y);
        out[2 * i + 1] = __floats2half2_rn(v.z, v.w);
    }
}

// Wh[n][k] = (half)W[k][n] : transpose to K-major for the B fragment
__global__ void cvt_transpose_h(const float* __restrict__ W, __half* __restrict__ Wt) {
    __shared__ float t[32][33];
    int k0 = blockIdx.y * 32, n0 = blockIdx.x * 32;
    int tx = threadIdx.x, ty = threadIdx.y;
#pragma unroll
    for (int i = 0; i < 32; i += 8)
        t[ty + i][tx] = W[(size_t)(k0 + ty + i) * Dd + n0 + tx];
    __syncthreads();
#pragma unroll
    for (int i = 0; i < 32; i += 8)
        Wt[(size_t)(n0 + ty + i) * Dd + k0 + tx] = __float2half_rn(t[tx][ty + i]);
}

// ===========================================================================
// fp16 GEMM: C[M,1024] = A[M,1024](half,row) @ Wt^T(half,[n][k]) + bias(f32)
// CTA 128x128x32, 8 warps (2x4), warp 64x32, double-buffered cp.async, LDSM.
// ===========================================================================
constexpr int HST = 40;   // smem row stride in halves (80B; LDSM conflict-free)
constexpr int GEMM_SMEM_H = 2 * (128 * HST + 128 * HST) * 2;  // 40960 B

DEVI void gemm_load_h(__half* As, __half* Bs, const __half* A, const __half* Bw,
                      int bm, int bn, int kt, int buf, int tid) {
#pragma unroll
    for (int i = 0; i < 2; i++) {
        int u = tid + 256 * i;
        int row = u >> 2, cc = (u & 3) * 8;
        cp16(&As[buf * 128 * HST + row * HST + cc],
             A + (size_t)(bm + row) * Dd + kt * 32 + cc);
        cp16(&Bs[buf * 128 * HST + row * HST + cc],
             Bw + (size_t)(bn + row) * Dd + kt * 32 + cc);
    }
    cpcommit();
}

template <typename OutT>
__global__ void __launch_bounds__(256, 2)
gemm_h(const __half* __restrict__ A, const __half* __restrict__ Bw,
       const float* __restrict__ bias, OutT* __restrict__ C) {
    extern __shared__ __half smh[];
    __half* As = smh;                    // [2][128*HST]
    __half* Bs = smh + 2 * 128 * HST;    // [2][128*HST]

    const int tid = threadIdx.x, lane = tid & 31, w = tid >> 5;
    const int wr = w >> 2, wc = w & 3, g = lane >> 2, tg = lane & 3;
    const int bm = blockIdx.y * 128, bn = blockIdx.x * 128;
    const int NK = Dd / 32;

    const uint32_t as_u = smem_u32(As), bs_u = smem_u32(Bs);
    // per-lane LDSM offsets (bytes)
    const uint32_t aoff = (((lane & 15) + wr * 64) * HST + (lane >> 4) * 8) * 2;
    const uint32_t boff = (((lane & 7) + wc * 32) * HST + ((lane >> 3) & 1) * 8) * 2;
    const uint32_t bufstep = 128 * HST * 2;

    float acc[4][4][4];
#pragma unroll
    for (int i = 0; i < 4; i++)
#pragma unroll
        for (int j = 0; j < 4; j++)
#pragma unroll
            for (int r = 0; r < 4; r++) acc[i][j][r] = 0.f;

    gemm_load_h(As, Bs, A, Bw, bm, bn, 0, 0, tid);

    for (int kt = 0; kt < NK; kt++) {
        if (kt + 1 < NK) {
            gemm_load_h(As, Bs, A, Bw, bm, bn, kt + 1, (kt + 1) & 1, tid);
            cpwait1();
        } else {
            cpwait0();
        }
        __syncthreads();

        const uint32_t abase = as_u + (kt & 1) * bufstep + aoff;
        const uint32_t bbase = bs_u + (kt & 1) * bufstep + boff;
#pragma unroll
        for (int ks = 0; ks < 2; ks++) {
            uint32_t af[4][4];
#pragma unroll
            for (int mt = 0; mt < 4; mt++)
                ldsm4(af[mt][0], af[mt][1], af[mt][2], af[mt][3],
                      abase + (mt * 16 * HST + ks * 16) * 2);
#pragma unroll
            for (int nt = 0; nt < 4; nt++) {
                uint32_t b0, b1;
                ldsm2(b0, b1, bbase + (nt * 8 * HST + ks * 16) * 2);
#pragma unroll
                for (int mt = 0; mt < 4; mt++)
                    mma_h(acc[mt][nt], af[mt][0], af[mt][1], af[mt][2], af[mt][3], b0, b1);
            }
        }
        __syncthreads();
    }

    // Epilogue: + bias, store (half2 or float2)
#pragma unroll
    for (int mt = 0; mt < 4; mt++) {
        int r0 = bm + wr * 64 + mt * 16 + g;
#pragma unroll
        for (int nt = 0; nt < 4; nt++) {
            int col = bn + wc * 32 + nt * 8 + 2 * tg;
            float b0v = bias[col], b1v = bias[col + 1];
            if (sizeof(OutT) == 2) {
                __half2* c0p = (__half2*)((__half*)C + (size_t)r0 * Dd + col);
                __half2* c1p = (__half2*)((__half*)C + (size_t)(r0 + 8) * Dd + col);
                *c0p = __floats2half2_rn(acc[mt][nt][0] + b0v, acc[mt][nt][1] + b1v);
                *c1p = __floats2half2_rn(acc[mt][nt][2] + b0v, acc[mt][nt][3] + b1v);
            } else {
                *(float2*)((float*)C + (size_t)r0 * Dd + col) =
                    make_float2(acc[mt][nt][0] + b0v, acc[mt][nt][1] + b1v);
                *(float2*)((float*)C + (size_t)(r0 + 8) * Dd + col) =
                    make_float2(acc[mt][nt][2] + b0v, acc[mt][nt][3] + b1v);
            }
        }
    }
}

// ===========================================================================
// Flash attention, fp16 mma + LDSM. One CTA = 256 query rows of one (b,h).
// P stays in registers (C-frag == A-frag after half2 pack).
// V row-major; PV B-frags via ldmatrix.trans.
// ===========================================================================
constexpr int QT = 256, KT = 64;
constexpr int QSP = 72, KSP = 72;  // smem strides (halves); LDSM conflict-free
constexpr int ATTN_SMEM = (QT * QSP + KT * KSP + KT * KSP) * 2;  // ~55 KB

__global__ void __launch_bounds__(256, 1)
attn_h(const __half* __restrict__ Qg, const __half* __restrict__ Kg,
       const __half* __restrict__ Vg, __half* __restrict__ Og) {
    extern __shared__ __half smh[];
    __half* Qs = smh;                    // [QT][QSP]
    __half* Ks = Qs + QT * QSP;          // [KT][KSP]  row = kv pos, col = dim
    __half* Vs = Ks + KT * KSP;          // [KT][KSP]  row = kv pos, col = dim

    const int tid = threadIdx.x, lane = tid & 31, w = tid >> 5;
    const int g = lane >> 2, tg = lane & 3;
    const int wrow = w * 32;
    const int bh = blockIdx.y, b = bh >> 4, h = bh & 15;
    const int q0 = blockIdx.x * QT;
    const size_t baseQ = ((size_t)b * Ss + q0) * Dd + h * DK;
    const size_t baseKV = ((size_t)b * Ss) * Dd + h * DK;

    const float qs = 1.4426950408889634f * 0.125f;  // log2(e)/sqrt(64)

    const uint4* Qv = (const uint4*)(Qg + baseQ);
    const uint4* Kv = (const uint4*)(Kg + baseKV);
    const uint4* Vv = (const uint4*)(Vg + baseKV);

    const uint32_t qs_u = smem_u32(Qs), ks_u = smem_u32(Ks), vs_u = smem_u32(Vs);
    // per-lane LDSM offsets (bytes)
    const uint32_t qoff = ((wrow + (lane & 15)) * QSP + (lane >> 4) * 8) * 2;
    const uint32_t koff = ((lane & 7) * KSP + ((lane >> 3) & 1) * 8) * 2;
    const uint32_t voff = ((((lane >> 3) & 1) * 8 + (lane & 7)) * KSP) * 2;

    // ---- load Q tile (256 x 64 halves)
#pragma unroll
    for (int i = 0; i < 8; i++) {
        int u = tid + i * 256;
        int r = u >> 3, cu = u & 7;
        uint4 t = Qv[(size_t)r * 128 + cu];
        *(uint4*)(Qs + r * QSP + cu * 8) = t;
    }

    uint4 kreg[2], vreg[2];
#pragma unroll
    for (int i = 0; i < 2; i++) {
        int u = tid + i * 256;
        int r = u >> 3, cu = u & 7;
        kreg[i] = Kv[(size_t)r * 128 + cu];
        vreg[i] = Vv[(size_t)r * 128 + cu];
    }
#pragma unroll
    for (int i = 0; i < 2; i++) {
        int u = tid + i * 256;
        int r = u >> 3, cu = u & 7;
        *(uint4*)(Ks + r * KSP + cu * 8) = kreg[i];
        *(uint4*)(Vs + r * KSP + cu * 8) = vreg[i];
    }
    __syncthreads();

    float ofr[2][8][4];
#pragma unroll
    for (int i = 0; i < 2; i++)
#pragma unroll
        for (int j = 0; j < 8; j++)
#pragma unroll
            for (int r = 0; r < 4; r++) ofr[i][j][r] = 0.f;
    float mrow[2][2] = {{-1e30f, -1e30f}, {-1e30f, -1e30f}};
    float lrow[2][2] = {{0.f, 0.f}, {0.f, 0.f}};

    const int NT = Ss / KT;  // 32
    for (int kt = 0; kt < NT; kt++) {
        // prefetch next K/V tile into registers (hidden behind compute)
        if (kt + 1 < NT) {
#pragma unroll
            for (int i = 0; i < 2; i++) {
                int u = tid + i * 256;
                int r = u >> 3, cu = u & 7;
                kreg[i] = Kv[(size_t)((kt + 1) * KT + r) * 128 + cu];
                vreg[i] = Vv[(size_t)((kt + 1) * KT + r) * 128 + cu];
            }
        }

        // ---- S = Q @ K^T (raw scores, fp32 accum)
        float sfr[2][8][4];
#pragma unroll
        for (int i = 0; i < 2; i++)
#pragma unroll
            for (int j = 0; j < 8; j++)
#pragma unroll
                for (int r = 0; r < 4; r++) sfr[i][j][r] = 0.f;

#pragma unroll
        for (int ks = 0; ks < 4; ks++) {
            uint32_t af[2][4];
#pragma unroll
            for (int mt = 0; mt < 2; mt++)
                ldsm4(af[mt][0], af[mt][1], af[mt][2], af[mt][3],
                      qs_u + qoff + (mt * 16 * QSP + ks * 16) * 2);
#pragma unroll
            for (int nt = 0; nt < 8; nt++) {
                uint32_t b0, b1;
                ldsm2(b0, b1, ks_u + koff + (nt * 8 * KSP + ks * 16) * 2);
                mma_h(sfr[0][nt], af[0][0], af[0][1], af[0][2], af[0][3], b0, b1);
                mma_h(sfr[1][nt], af[1][0], af[1][1], af[1][2], af[1][3], b0, b1);
            }
        }

        // ---- online softmax (scale folded into exp2: p = 2^((s-m)*qs))
#pragma unroll
        for (int mt = 0; mt < 2; mt++) {
#pragma unroll
            for (int hf = 0; hf < 2; hf++) {
                float mx = -1e30f;
#pragma unroll
                for (int nt = 0; nt < 8; nt++)
                    mx = fmaxf(mx, fmaxf(sfr[mt][nt][2 * hf], sfr[mt][nt][2 * hf + 1]));
                mx = fmaxf(mx, __shfl_xor_sync(0xffffffffu, mx, 1));
                mx = fmaxf(mx, __shfl_xor_sync(0xffffffffu, mx, 2));
                float mo = mrow[mt][hf];
                float mn = fmaxf(mo, mx);
                float mq = mn * qs;
                float al = ex2f(fmaf(mo, qs, -mq));
                float sum = 0.f;
#pragma unroll
                for (int nt = 0; nt < 8; nt++) {
                    float p0 = ex2f(fmaf(sfr[mt][nt][2 * hf], qs, -mq));
                    float p1 = ex2f(fmaf(sfr[mt][nt][2 * hf + 1], qs, -mq));
                    sfr[mt][nt][2 * hf] = p0;
                    sfr[mt][nt][2 * hf + 1] = p1;
                    sum += p0 + p1;
                }
                sum += __shfl_xor_sync(0xffffffffu, sum, 1);
                sum += __shfl_xor_sync(0xffffffffu, sum, 2);
                lrow[mt][hf] = lrow[mt][hf] * al + sum;
                mrow[mt][hf] = mn;
#pragma unroll
                for (int nt = 0; nt < 8; nt++) {
                    ofr[mt][nt][2 * hf] *= al;
                    ofr[mt][nt][2 * hf + 1] *= al;
                }
            }
        }

        // ---- O += P @ V : P fragments直接 from sfr (C-frag == A-frag layout)
#pragma unroll
        for (int ks = 0; ks < 4; ks++) {
            uint32_t af[2][4];
#pragma unroll
            for (int mt = 0; mt < 2; mt++) {
                af[mt][0] = h2u(__floats2half2_rn(sfr[mt][2 * ks][0], sfr[mt][2 * ks][1]));
                af[mt][1] = h2u(__floats2half2_rn(sfr[mt][2 * ks][2], sfr[mt][2 * ks][3]));
                af[mt][2] = h2u(__floats2half2_rn(sfr[mt][2 * ks + 1][0], sfr[mt][2 * ks + 1][1]));
                af[mt][3] = h2u(__floats2half2_rn(sfr[mt][2 * ks + 1][2], sfr[mt][2 * ks + 1][3]));
            }
#pragma unroll
            for (int nt = 0; nt < 8; nt++) {
                uint32_t b0, b1;
                ldsm2t(b0, b1, vs_u + voff + (ks * 16 * KSP + nt * 8) * 2);
                mma_h(ofr[0][nt], af[0][0], af[0][1], af[0][2], af[0][3], b0, b1);
                mma_h(ofr[1][nt], af[1][0], af[1][1], af[1][2], af[1][3], b0, b1);
            }
        }

        // ---- publish next K/V tile
        if (kt + 1 < NT) {
            __syncthreads();
#pragma unroll
            for (int i = 0; i < 2; i++) {
                int u = tid + i * 256;
                int r = u >> 3, cu = u & 7;
                *(uint4*)(Ks + r * KSP + cu * 8) = kreg[i];
                *(uint4*)(Vs + r * KSP + cu * 8) = vreg[i];
            }
            __syncthreads();
        }
    }

    // ---- normalize + write [B,S,D] half
#pragma unroll
    for (int mt = 0; mt < 2; mt++)
#pragma unroll
        for (int hf = 0; hf < 2; hf++) {
            float inv = 1.f / lrow[mt][hf];
            int r = q0 + wrow + mt * 16 + g + hf * 8;
            __half* op = Og + ((size_t)b * Ss + r) * Dd + h * DK;
#pragma unroll
            for (int nt = 0; nt < 8; nt++)
                *(uint32_t*)(op + nt * 8 + 2 * tg) =
                    h2u(__floats2half2_rn(ofr[mt][nt][2 * hf] * inv,
                                          ofr[mt][nt][2 * hf + 1] * inv));
        }
}

// ===========================================================================
// Launch
// ===========================================================================
extern "C" void kernel_launch(void* const* d_in, const int* in_sizes, int n_in,
                              void* d_out, int out_size) {
    const float* q  = (const float*)d_in[0];
    const float* k  = (const float*)d_in[1];
    const float* v  = (const float*)d_in[2];
    const float* wq = (const float*)d_in[3];
    const float* bq = (const float*)d_in[4];
    const float* wk = (const float*)d_in[5];
    const float* bk = (const float*)d_in[6];
    const float* wv = (const float*)d_in[7];
    const float* bv = (const float*)d_in[8];
    const float* wo = (const float*)d_in[9];
    const float* bo = (const float*)d_in[10];
    float* out = (float*)d_out;

    __half *Qh, *Kh, *Vh, *Ah, *Xh, *Wh;
    cudaGetSymbolAddress((void**)&Qh, g_Qh);
    cudaGetSymbolAddress((void**)&Kh, g_Kh);
    cudaGetSymbolAddress((void**)&Vh, g_Vh);
    cudaGetSymbolAddress((void**)&Ah, g_Ah);
    cudaGetSymbolAddress((void**)&Xh, g_Xh);
    cudaGetSymbolAddress((void**)&Wh, g_Wh);

    cudaFuncSetAttribute(gemm_h<__half>, cudaFuncAttributeMaxDynamicSharedMemorySize, GEMM_SMEM_H);
    cudaFuncSetAttribute(gemm_h<float>, cudaFuncAttributeMaxDynamicSharedMemorySize, GEMM_SMEM_H);
    cudaFuncSetAttribute(attn_h, cudaFuncAttributeMaxDynamicSharedMemorySize, ATTN_SMEM);

    const int n4 = Mrows * Dd / 4;
    dim3 tgrid(Dd / 32, Dd / 32), tblk(32, 8);
    dim3 gg(Dd / 128, Mrows / 128);  // (8, 64)
    dim3 ga(Ss / QT, Bb * Hh);       // (8, 64)

    // Q projection
    cvt_transpose_h<<<tgrid, tblk>>>(wq, Wh);
    cvt_h<<<1184, 256>>>((const float4*)q, (__half2*)Xh, n4);
    gemm_h<__half><<<gg, 256, GEMM_SMEM_H>>>(Xh, Wh, bq, Qh);

    // K projection
    cvt_transpose_h<<<tgrid, tblk>>>(wk, Wh);
    cvt_h<<<1184, 256>>>((const float4*)k, (__half2*)Xh, n4);
    gemm_h<__half><<<gg, 256, GEMM_SMEM_H>>>(Xh, Wh, bk, Kh);

    // V projection
    cvt_transpose_h<<<tgrid, tblk>>>(wv, Wh);
    cvt_h<<<1184, 256>>>((const float4*)v, (__half2*)Xh, n4);
    gemm_h<__half><<<gg, 256, GEMM_SMEM_H>>>(Xh, Wh, bv, Vh);

    // Attention
    attn_h<<<ga, 256, ATTN_SMEM>>>(Qh, Kh, Vh, Ah);

    // Output projection (fp32 out)
    cvt_transpose_h<<<tgrid, tblk>>>(wo, Wh);
    gemm_h<float><<<gg, 256, GEMM_SMEM_H>>>(Ah, Wh, bo, out);
}

// round 17
// speedup vs baseline: 1.8896x; 1.0324x over previous
#include <cuda_runtime.h>
#include <cuda_fp16.h>
#include <cstdint>

// Problem constants
constexpr int Bb = 4, Ss = 2048, Dd = 1024, Hh = 16, DK = 64;
constexpr int Mrows = Bb * Ss;  // 8192

// Scratch (static device arrays: allocation-free rule)
static __device__ __half g_Qh[Mrows * Dd];
static __device__ __half g_Kh[Mrows * Dd];
static __device__ __half g_Vh[Mrows * Dd];
static __device__ __half g_Ah[Mrows * Dd];       // attention output (fp16)
static __device__ __half g_W4[4 * Dd * Dd];      // 4 converted+transposed weights [n][k]

#define DEVI __device__ __forceinline__

DEVI float ex2f(float x) {
    float r;
    asm("ex2.approx.f32 %0, %1;" : "=f"(r) : "f"(x));
    return r;
}

// fp16 MMA: D(16x8,f32) += A(16x16,f16 row) * B(16x8,f16 col)
DEVI void mma_h(float* c, uint32_t a0, uint32_t a1, uint32_t a2, uint32_t a3,
                uint32_t b0, uint32_t b1) {
    asm volatile(
        "mma.sync.aligned.m16n8k16.row.col.f32.f16.f16.f32 "
        "{%0,%1,%2,%3},{%4,%5,%6,%7},{%8,%9},{%0,%1,%2,%3};"
        : "+f"(c[0]), "+f"(c[1]), "+f"(c[2]), "+f"(c[3])
        : "r"(a0), "r"(a1), "r"(a2), "r"(a3), "r"(b0), "r"(b1));
}

DEVI void ldsm4(uint32_t& r0, uint32_t& r1, uint32_t& r2, uint32_t& r3, uint32_t saddr) {
    asm volatile("ldmatrix.sync.aligned.m8n8.x4.shared.b16 {%0,%1,%2,%3}, [%4];"
                 : "=r"(r0), "=r"(r1), "=r"(r2), "=r"(r3) : "r"(saddr));
}
DEVI void ldsm2(uint32_t& r0, uint32_t& r1, uint32_t saddr) {
    asm volatile("ldmatrix.sync.aligned.m8n8.x2.shared.b16 {%0,%1}, [%2];"
                 : "=r"(r0), "=r"(r1) : "r"(saddr));
}
DEVI void ldsm2t(uint32_t& r0, uint32_t& r1, uint32_t saddr) {
    asm volatile("ldmatrix.sync.aligned.m8n8.x2.trans.shared.b16 {%0,%1}, [%2];"
                 : "=r"(r0), "=r"(r1) : "r"(saddr));
}

DEVI void cp16(void* smem, const void* g) {
    uint32_t s = (uint32_t)__cvta_generic_to_shared(smem);
    asm volatile("cp.async.cg.shared.global [%0], [%1], 16;\n" ::"r"(s), "l"(g));
}
DEVI void cpcommit() { asm volatile("cp.async.commit_group;\n"); }
DEVI void cpwait0() { asm volatile("cp.async.wait_group 0;\n" ::: "memory"); }
DEVI void cpwait1() { asm volatile("cp.async.wait_group 1;\n" ::: "memory"); }

DEVI uint32_t h2u(__half2 h) { return *reinterpret_cast<uint32_t*>(&h); }
DEVI uint32_t smem_u32(const void* p) {
    uint32_t a;
    asm("{ .reg .u64 t; cvta.to.shared.u64 t, %1; cvt.u32.u64 %0, t; }" : "=r"(a) : "l"(p));
    return a;
}

// ===========================================================================
// Batched weight convert+transpose: W4[z][n][k] = (half)Wz[k][n]
// ===========================================================================
__global__ void cvt_transpose4(const float* __restrict__ w0, const float* __restrict__ w1,
                               const float* __restrict__ w2, const float* __restrict__ w3,
                               __half* __restrict__ Wt) {
    __shared__ float t[32][33];
    const float* W = blockIdx.z == 0 ? w0 : blockIdx.z == 1 ? w1 : blockIdx.z == 2 ? w2 : w3;
    __half* dst = Wt + (size_t)blockIdx.z * Dd * Dd;
    int k0 = blockIdx.y * 32, n0 = blockIdx.x * 32;
    int tx = threadIdx.x, ty = threadIdx.y;
#pragma unroll
    for (int i = 0; i < 32; i += 8)
        t[ty + i][tx] = W[(size_t)(k0 + ty + i) * Dd + n0 + tx];
    __syncthreads();
#pragma unroll
    for (int i = 0; i < 32; i += 8)
        dst[(size_t)(n0 + ty + i) * Dd + k0 + tx] = __float2half_rn(t[tx][ty + i]);
}

// ===========================================================================
// fp16 GEMM with fused A conversion:
//   C[M,1024] = cvt(A[M,1024], InT) @ Wt^T(half,[n][k]) + bias(f32)
// CTA 128x128x32, 8 warps (2x4). A: register-prefetch LDG (+cvt if fp32) -> STS
// (single smem buffer); B: cp.async double-buffered. LDSM fragments.
// ===========================================================================
constexpr int HST = 40;   // smem row stride in halves (80B; LDSM conflict-free)
constexpr int GEMM_SMEM_H = (128 * HST + 2 * 128 * HST) * 2;  // 30720 B

DEVI void gemm_loadB(__half* Bs, const __half* Bw, int bn, int kt, int buf, int tid) {
#pragma unroll
    for (int i = 0; i < 2; i++) {
        int u = tid + 256 * i;
        int row = u >> 2, cc = (u & 3) * 8;
        cp16(&Bs[buf * 128 * HST + row * HST + cc],
             Bw + (size_t)(bn + row) * Dd + kt * 32 + cc);
    }
    cpcommit();
}

template <typename InT, typename OutT>
__global__ void __launch_bounds__(256, 2)
gemm_h(const InT* __restrict__ A, const __half* __restrict__ Bw,
       const float* __restrict__ bias, OutT* __restrict__ C) {
    extern __shared__ __half smh[];
    __half* As = smh;                    // [128*HST] single buffer
    __half* Bs = smh + 128 * HST;        // [2][128*HST]

    const int tid = threadIdx.x, lane = tid & 31, w = tid >> 5;
    const int wr = w >> 2, wc = w & 3, g = lane >> 2, tg = lane & 3;
    const int bm = blockIdx.y * 128, bn = blockIdx.x * 128;
    const int NK = Dd / 32;

    // A prefetch geometry: each thread owns 16 consecutive elements of one row
    const int arow = tid >> 1, aseg = (tid & 1) * 16;
    const InT* Ap = A + (size_t)(bm + arow) * Dd + aseg;

    const uint32_t as_u = smem_u32(As), bs_u = smem_u32(Bs);
    const uint32_t aoff = (((lane & 15) + wr * 64) * HST + (lane >> 4) * 8) * 2;
    const uint32_t boff = (((lane & 7) + wc * 32) * HST + ((lane >> 3) & 1) * 8) * 2;
    const uint32_t bufstep = 128 * HST * 2;
    __half* AsT = As + arow * HST + aseg;

    float acc[4][4][4];
#pragma unroll
    for (int i = 0; i < 4; i++)
#pragma unroll
        for (int j = 0; j < 4; j++)
#pragma unroll
            for (int r = 0; r < 4; r++) acc[i][j][r] = 0.f;

    // Prologue: A(0) into regs, B(0) via cp.async
    float4 arf[4];
    uint4 arh[2];
    if (sizeof(InT) == 4) {
#pragma unroll
        for (int i = 0; i < 4; i++) arf[i] = *(const float4*)((const float*)Ap + 4 * i);
    } else {
#pragma unroll
        for (int i = 0; i < 2; i++) arh[i] = *(const uint4*)((const __half*)Ap + 8 * i);
    }
    gemm_loadB(Bs, Bw, bn, 0, 0, tid);

    for (int kt = 0; kt < NK; kt++) {
        const int buf = kt & 1;
        // publish A(kt): convert + STS (prev compute finished at trailing sync)
        if (sizeof(InT) == 4) {
            uint4 s0, s1;
            s0.x = h2u(__floats2half2_rn(arf[0].x, arf[0].y));
            s0.y = h2u(__floats2half2_rn(arf[0].z, arf[0].w));
            s0.z = h2u(__floats2half2_rn(arf[1].x, arf[1].y));
            s0.w = h2u(__floats2half2_rn(arf[1].z, arf[1].w));
            s1.x = h2u(__floats2half2_rn(arf[2].x, arf[2].y));
            s1.y = h2u(__floats2half2_rn(arf[2].z, arf[2].w));
            s1.z = h2u(__floats2half2_rn(arf[3].x, arf[3].y));
            s1.w = h2u(__floats2half2_rn(arf[3].z, arf[3].w));
            *(uint4*)(AsT) = s0;
            *(uint4*)(AsT + 8) = s1;
        } else {
            *(uint4*)(AsT) = arh[0];
            *(uint4*)(AsT + 8) = arh[1];
        }
        if (kt + 1 < NK) {
            // prefetch A(kt+1) regs; launch B(kt+1)
            if (sizeof(InT) == 4) {
#pragma unroll
                for (int i = 0; i < 4; i++)
                    arf[i] = *(const float4*)((const float*)Ap + (kt + 1) * 32 + 4 * i);
            } else {
#pragma unroll
                for (int i = 0; i < 2; i++)
                    arh[i] = *(const uint4*)((const __half*)Ap + (kt + 1) * 32 + 8 * i);
            }
            gemm_loadB(Bs, Bw, bn, kt + 1, buf ^ 1, tid);
            cpwait1();
        } else {
            cpwait0();
        }
        __syncthreads();

        const uint32_t bbase = bs_u + buf * bufstep + boff;
#pragma unroll
        for (int ks = 0; ks < 2; ks++) {
            uint32_t af[4][4];
#pragma unroll
            for (int mt = 0; mt < 4; mt++)
                ldsm4(af[mt][0], af[mt][1], af[mt][2], af[mt][3],
                      as_u + aoff + (mt * 16 * HST + ks * 16) * 2);
#pragma unroll
            for (int nt = 0; nt < 4; nt++) {
                uint32_t b0, b1;
                ldsm2(b0, b1, bbase + (nt * 8 * HST + ks * 16) * 2);
#pragma unroll
                for (int mt = 0; mt < 4; mt++)
                    mma_h(acc[mt][nt], af[mt][0], af[mt][1], af[mt][2], af[mt][3], b0, b1);
            }
        }
        __syncthreads();
    }

    // Epilogue: + bias, store
#pragma unroll
    for (int mt = 0; mt < 4; mt++) {
        int r0 = bm + wr * 64 + mt * 16 + g;
#pragma unroll
        for (int nt = 0; nt < 4; nt++) {
            int col = bn + wc * 32 + nt * 8 + 2 * tg;
            float b0v = bias[col], b1v = bias[col + 1];
            if (sizeof(OutT) == 2) {
                __half2* c0p = (__half2*)((__half*)C + (size_t)r0 * Dd + col);
                __half2* c1p = (__half2*)((__half*)C + (size_t)(r0 + 8) * Dd + col);
                *c0p = __floats2half2_rn(acc[mt][nt][0] + b0v, acc[mt][nt][1] + b1v);
                *c1p = __floats2half2_rn(acc[mt][nt][2] + b0v, acc[mt][nt][3] + b1v);
            } else {
                *(float2*)((float*)C + (size_t)r0 * Dd + col) =
                    make_float2(acc[mt][nt][0] + b0v, acc[mt][nt][1] + b1v);
                *(float2*)((float*)C + (size_t)(r0 + 8) * Dd + col) =
                    make_float2(acc[mt][nt][2] + b0v, acc[mt][nt][3] + b1v);
            }
        }
    }
}

// ===========================================================================
// Flash attention, fp16 mma + LDSM. QT=128 (16 rows/warp) -> 2 CTAs/SM.
// P stays in registers (C-frag == A-frag). V row-major; PV B via ldmatrix.trans.
// ===========================================================================
constexpr int QT = 128, KT = 64;
constexpr int QSP = 72, KSP = 72;
constexpr int ATTN_SMEM = (QT * QSP + KT * KSP + KT * KSP) * 2;  // 36864 B

__global__ void __launch_bounds__(256, 2)
attn_h(const __half* __restrict__ Qg, const __half* __restrict__ Kg,
       const __half* __restrict__ Vg, __half* __restrict__ Og) {
    extern __shared__ __half smh[];
    __half* Qs = smh;                    // [QT][QSP]
    __half* Ks = Qs + QT * QSP;          // [KT][KSP]
    __half* Vs = Ks + KT * KSP;          // [KT][KSP]

    const int tid = threadIdx.x, lane = tid & 31, w = tid >> 5;
    const int g = lane >> 2, tg = lane & 3;
    const int wrow = w * 16;
    const int bh = blockIdx.y, b = bh >> 4, h = bh & 15;
    const int q0 = blockIdx.x * QT;
    const size_t baseQ = ((size_t)b * Ss + q0) * Dd + h * DK;
    const size_t baseKV = ((size_t)b * Ss) * Dd + h * DK;

    const float qs = 1.4426950408889634f * 0.125f;  // log2(e)/sqrt(64)

    const uint4* Qv = (const uint4*)(Qg + baseQ);
    const uint4* Kv = (const uint4*)(Kg + baseKV);
    const uint4* Vv = (const uint4*)(Vg + baseKV);

    const uint32_t qs_u = smem_u32(Qs), ks_u = smem_u32(Ks), vs_u = smem_u32(Vs);
    const uint32_t qoff = ((wrow + (lane & 15)) * QSP + (lane >> 4) * 8) * 2;
    const uint32_t koff = ((lane & 7) * KSP + ((lane >> 3) & 1) * 8) * 2;
    const uint32_t voff = ((((lane >> 3) & 1) * 8 + (lane & 7)) * KSP) * 2;

    // ---- load Q tile (128 x 64 halves): 4 uint4/thread
#pragma unroll
    for (int i = 0; i < 4; i++) {
        int u = tid + i * 256;
        int r = u >> 3, cu = u & 7;
        uint4 t = Qv[(size_t)r * 128 + cu];
        *(uint4*)(Qs + r * QSP + cu * 8) = t;
    }

    uint4 kreg[2], vreg[2];
#pragma unroll
    for (int i = 0; i < 2; i++) {
        int u = tid + i * 256;
        int r = u >> 3, cu = u & 7;
        kreg[i] = Kv[(size_t)r * 128 + cu];
        vreg[i] = Vv[(size_t)r * 128 + cu];
    }
#pragma unroll
    for (int i = 0; i < 2; i++) {
        int u = tid + i * 256;
        int r = u >> 3, cu = u & 7;
        *(uint4*)(Ks + r * KSP + cu * 8) = kreg[i];
        *(uint4*)(Vs + r * KSP + cu * 8) = vreg[i];
    }
    __syncthreads();

    float ofr[8][4];
#pragma unroll
    for (int j = 0; j < 8; j++)
#pragma unroll
        for (int r = 0; r < 4; r++) ofr[j][r] = 0.f;
    float mrow[2] = {-1e30f, -1e30f};
    float lrow[2] = {0.f, 0.f};

    const int NT = Ss / KT;  // 32
    for (int kt = 0; kt < NT; kt++) {
        if (kt + 1 < NT) {
#pragma unroll
            for (int i = 0; i < 2; i++) {
                int u = tid + i * 256;
                int r = u >> 3, cu = u & 7;
                kreg[i] = Kv[(size_t)((kt + 1) * KT + r) * 128 + cu];
                vreg[i] = Vv[(size_t)((kt + 1) * KT + r) * 128 + cu];
            }
        }

        // ---- S = Q @ K^T
        float sfr[8][4];
#pragma unroll
        for (int j = 0; j < 8; j++)
#pragma unroll
            for (int r = 0; r < 4; r++) sfr[j][r] = 0.f;

#pragma unroll
        for (int ks = 0; ks < 4; ks++) {
            uint32_t a0, a1, a2, a3;
            ldsm4(a0, a1, a2, a3, qs_u + qoff + (ks * 16) * 2);
#pragma unroll
            for (int nt = 0; nt < 8; nt++) {
                uint32_t b0, b1;
                ldsm2(b0, b1, ks_u + koff + (nt * 8 * KSP + ks * 16) * 2);
                mma_h(sfr[nt], a0, a1, a2, a3, b0, b1);
            }
        }

        // ---- online softmax
#pragma unroll
        for (int hf = 0; hf < 2; hf++) {
            float mx = -1e30f;
#pragma unroll
            for (int nt = 0; nt < 8; nt++)
                mx = fmaxf(mx, fmaxf(sfr[nt][2 * hf], sfr[nt][2 * hf + 1]));
            mx = fmaxf(mx, __shfl_xor_sync(0xffffffffu, mx, 1));
            mx = fmaxf(mx, __shfl_xor_sync(0xffffffffu, mx, 2));
            float mo = mrow[hf];
            float mn = fmaxf(mo, mx);
            float mq = mn * qs;
            float al = ex2f(fmaf(mo, qs, -mq));
            float sum = 0.f;
#pragma unroll
            for (int nt = 0; nt < 8; nt++) {
                float p0 = ex2f(fmaf(sfr[nt][2 * hf], qs, -mq));
                float p1 = ex2f(fmaf(sfr[nt][2 * hf + 1], qs, -mq));
                sfr[nt][2 * hf] = p0;
                sfr[nt][2 * hf + 1] = p1;
                sum += p0 + p1;
            }
            sum += __shfl_xor_sync(0xffffffffu, sum, 1);
            sum += __shfl_xor_sync(0xffffffffu, sum, 2);
            lrow[hf] = lrow[hf] * al + sum;
            mrow[hf] = mn;
#pragma unroll
            for (int nt = 0; nt < 8; nt++) {
                ofr[nt][2 * hf] *= al;
                ofr[nt][2 * hf + 1] *= al;
            }
        }

        // ---- O += P @ V  (P from sfr: C-frag == A-frag after half2 pack)
#pragma unroll
        for (int ks = 0; ks < 4; ks++) {
            uint32_t a0 = h2u(__floats2half2_rn(sfr[2 * ks][0], sfr[2 * ks][1]));
            uint32_t a1 = h2u(__floats2half2_rn(sfr[2 * ks][2], sfr[2 * ks][3]));
            uint32_t a2 = h2u(__floats2half2_rn(sfr[2 * ks + 1][0], sfr[2 * ks + 1][1]));
            uint32_t a3 = h2u(__floats2half2_rn(sfr[2 * ks + 1][2], sfr[2 * ks + 1][3]));
#pragma unroll
            for (int nt = 0; nt < 8; nt++) {
                uint32_t b0, b1;
                ldsm2t(b0, b1, vs_u + voff + (ks * 16 * KSP + nt * 8) * 2);
                mma_h(ofr[nt], a0, a1, a2, a3, b0, b1);
            }
        }

        // ---- publish next K/V tile
        if (kt + 1 < NT) {
            __syncthreads();
#pragma unroll
            for (int i = 0; i < 2; i++) {
                int u = tid + i * 256;
                int r = u >> 3, cu = u & 7;
                *(uint4*)(Ks + r * KSP + cu * 8) = kreg[i];
                *(uint4*)(Vs + r * KSP + cu * 8) = vreg[i];
            }
            __syncthreads();
        }
    }

    // ---- normalize + write [B,S,D] half
#pragma unroll
    for (int hf = 0; hf < 2; hf++) {
        float inv = 1.f / lrow[hf];
        int r = q0 + wrow + g + hf * 8;
        __half* op = Og + ((size_t)b * Ss + r) * Dd + h * DK;
#pragma unroll
        for (int nt = 0; nt < 8; nt++)
            *(uint32_t*)(op + nt * 8 + 2 * tg) =
                h2u(__floats2half2_rn(ofr[nt][2 * hf] * inv, ofr[nt][2 * hf + 1] * inv));
    }
}

// ===========================================================================
// Launch
// ===========================================================================
extern "C" void kernel_launch(void* const* d_in, const int* in_sizes, int n_in,
                              void* d_out, int out_size) {
    const float* q  = (const float*)d_in[0];
    const float* k  = (const float*)d_in[1];
    const float* v  = (const float*)d_in[2];
    const float* wq = (const float*)d_in[3];
    const float* bq = (const float*)d_in[4];
    const float* wk = (const float*)d_in[5];
    const float* bk = (const float*)d_in[6];
    const float* wv = (const float*)d_in[7];
    const float* bv = (const float*)d_in[8];
    const float* wo = (const float*)d_in[9];
    const float* bo = (const float*)d_in[10];
    float* out = (float*)d_out;

    __half *Qh, *Kh, *Vh, *Ah, *W4;
    cudaGetSymbolAddress((void**)&Qh, g_Qh);
    cudaGetSymbolAddress((void**)&Kh, g_Kh);
    cudaGetSymbolAddress((void**)&Vh, g_Vh);
    cudaGetSymbolAddress((void**)&Ah, g_Ah);
    cudaGetSymbolAddress((void**)&W4, g_W4);

    const size_t WS = (size_t)Dd * Dd;

    dim3 tgrid(Dd / 32, Dd / 32, 4), tblk(32, 8);
    dim3 gg(Dd / 128, Mrows / 128);  // (8, 64)
    dim3 ga(Ss / QT, Bb * Hh);       // (16, 64)

    // All 4 weights converted+transposed in one launch
    cvt_transpose4<<<tgrid, tblk>>>(wq, wk, wv, wo, W4);

    // Projections (A = fp32 inputs, converted in-kernel)
    gemm_h<float, __half><<<gg, 256, GEMM_SMEM_H>>>(q, W4 + 0 * WS, bq, Qh);
    gemm_h<float, __half><<<gg, 256, GEMM_SMEM_H>>>(k, W4 + 1 * WS, bk, Kh);
    gemm_h<float, __half><<<gg, 256, GEMM_SMEM_H>>>(v, W4 + 2 * WS, bv, Vh);

    // Attention
    attn_h<<<ga, 256, ATTN_SMEM>>>(Qh, Kh, Vh, Ah);

    // Output projection (A = fp16 attention output, fp32 out)
    gemm_h<__half, float><<<gg, 256, GEMM_SMEM_H>>>(Ah, W4 + 3 * WS, bo, out);
}